// round 3
// baseline (speedup 1.0000x reference)
#include <cuda_runtime.h>

// Reverse (suffix) cumulative sum along dim=1.
// x: (B=2048, N=32768) fp32. out[b, j] = sum_{k >= j} x[b, k].
//
// One CTA per row, 1024 threads, coalesced interleaved register layout
// (thread holds tile[i*32 + lane] for i=0..7, so every LDG.128/STG.128
// covers 4 contiguous 128B lines).
//
// R3 changes vs R2:
//   - __ldcs / __stcs streaming (evict-first) hints: pure streaming
//     workload, no reuse, keep L2 pressure down.
//   - single __syncthreads(): every warp redundantly scans the 32
//     warp totals via shfl and extracts its own offset, instead of
//     warp 0 computing offsets + a second barrier.

#define N_COLS      32768
#define THREADS     1024
#define F4_PER_WARP 256   // 1024 floats per warp tile
#define SLOTS       8     // float4s per thread

__global__ __launch_bounds__(THREADS, 1)
void revcumsum_kernel(const float* __restrict__ x, float* __restrict__ out) {
    const long long base = (long long)blockIdx.x * N_COLS;
    const int t    = threadIdx.x;
    const int lane = t & 31;
    const int wid  = t >> 5;

    const float4* __restrict__ xin =
        reinterpret_cast<const float4*>(x + base) + wid * F4_PER_WARP + lane;

    // ---- coalesced streaming load: slot i at float4 index i*32 + lane ----
    float4 r[SLOTS];
    #pragma unroll
    for (int i = 0; i < SLOTS; i++) r[i] = __ldcs(&xin[i * 32]);

    // ---- suffix scan inside each float4; s[i] = group sum ----
    float s[SLOTS];
    #pragma unroll
    for (int i = 0; i < SLOTS; i++) {
        r[i].z += r[i].w;
        r[i].y += r[i].z;
        r[i].x += r[i].y;
        s[i] = r[i].x;
    }

    // ---- per-slot warp suffix scan over lanes ----
    float excl[SLOTS];   // sum of s[i] for lanes > my lane
    float T[SLOTS];      // warp-wide total of slot i
    #pragma unroll
    for (int i = 0; i < SLOTS; i++) {
        float incl = s[i];
        #pragma unroll
        for (int d = 1; d < 32; d <<= 1) {
            float tmp = __shfl_down_sync(0xFFFFFFFFu, incl, d);
            if (lane + d < 32) incl += tmp;
        }
        excl[i] = incl - s[i];
        T[i]    = __shfl_sync(0xFFFFFFFFu, incl, 0);
    }

    // ---- register suffix over slots: O[i] = sum of T[i'] for i' > i ----
    float O[SLOTS];
    O[SLOTS - 1] = 0.0f;
    #pragma unroll
    for (int i = SLOTS - 2; i >= 0; i--) O[i] = O[i + 1] + T[i + 1];
    const float warp_total = O[0] + T[0];

    // ---- block suffix scan over warp totals: ONE barrier, every warp
    //      redundantly scans the 32 totals and picks its own offset ----
    __shared__ float warp_tot[32];
    if (lane == 0) warp_tot[wid] = warp_total;
    __syncthreads();
    {
        float w  = warp_tot[lane];
        float iw = w;
        #pragma unroll
        for (int d = 1; d < 32; d <<= 1) {
            float tmp = __shfl_down_sync(0xFFFFFFFFu, iw, d);
            if (lane + d < 32) iw += tmp;
        }
        // exclusive suffix (warps after lane) = iw - w; take lane == wid
        const float woff = __shfl_sync(0xFFFFFFFFu, iw - w, wid);

        // ---- apply offsets, coalesced streaming store ----
        float4* __restrict__ o =
            reinterpret_cast<float4*>(out + base) + wid * F4_PER_WARP + lane;
        #pragma unroll
        for (int i = 0; i < SLOTS; i++) {
            const float off = woff + O[i] + excl[i];
            float4 wv;
            wv.x = r[i].x + off;
            wv.y = r[i].y + off;
            wv.z = r[i].z + off;
            wv.w = r[i].w + off;
            __stcs(&o[i * 32], wv);
        }
    }
}

extern "C" void kernel_launch(void* const* d_in, const int* in_sizes, int n_in,
                              void* d_out, int out_size) {
    const float* x = (const float*)d_in[0];
    float* out = (float*)d_out;
    const int n = in_sizes[0];          // B * N
    const int rows = n / N_COLS;        // 2048
    revcumsum_kernel<<<rows, THREADS>>>(x, out);
}

// round 5
// speedup vs baseline: 1.1007x; 1.1007x over previous
#include <cuda_runtime.h>

// Reverse (suffix) cumulative sum along dim=1.
// x: (B=2048, N=32768) fp32. out[b, j] = sum_{k >= j} x[b, k].
//
// One CTA per row, 1024 threads, coalesced interleaved register layout
// (thread holds tile[i*32 + lane] for i=0..7, so every LDG.128/STG.128
// covers 4 contiguous 128B lines => full-width L1 wavefronts).
//
// R4 = R2 memory path (DEFAULT cache policy — the R3 .cs hints cost 9us)
//      + single-barrier block scan (every warp redundantly scans the 32
//      warp totals via shfl and extracts its own offset; no 2nd barrier).

#define N_COLS      32768
#define THREADS     1024
#define F4_PER_WARP 256   // 1024 floats per warp tile
#define SLOTS       8     // float4s per thread

__global__ __launch_bounds__(THREADS, 1)
void revcumsum_kernel(const float* __restrict__ x, float* __restrict__ out) {
    const long long base = (long long)blockIdx.x * N_COLS;
    const int t    = threadIdx.x;
    const int lane = t & 31;
    const int wid  = t >> 5;

    const float4* __restrict__ xin =
        reinterpret_cast<const float4*>(x + base) + wid * F4_PER_WARP + lane;

    // ---- coalesced load: slot i at float4 index i*32 + lane ----
    float4 r[SLOTS];
    #pragma unroll
    for (int i = 0; i < SLOTS; i++) r[i] = xin[i * 32];

    // ---- suffix scan inside each float4; s[i] = group sum ----
    float s[SLOTS];
    #pragma unroll
    for (int i = 0; i < SLOTS; i++) {
        r[i].z += r[i].w;
        r[i].y += r[i].z;
        r[i].x += r[i].y;
        s[i] = r[i].x;
    }

    // ---- per-slot warp suffix scan over lanes ----
    float excl[SLOTS];   // sum of s[i] for lanes > my lane
    float T[SLOTS];      // warp-wide total of slot i
    #pragma unroll
    for (int i = 0; i < SLOTS; i++) {
        float incl = s[i];
        #pragma unroll
        for (int d = 1; d < 32; d <<= 1) {
            float tmp = __shfl_down_sync(0xFFFFFFFFu, incl, d);
            if (lane + d < 32) incl += tmp;
        }
        excl[i] = incl - s[i];
        T[i]    = __shfl_sync(0xFFFFFFFFu, incl, 0);
    }

    // ---- register suffix over slots: O[i] = sum of T[i'] for i' > i ----
    float O[SLOTS];
    O[SLOTS - 1] = 0.0f;
    #pragma unroll
    for (int i = SLOTS - 2; i >= 0; i--) O[i] = O[i + 1] + T[i + 1];
    const float warp_total = O[0] + T[0];

    // ---- block suffix scan over warp totals: ONE barrier, every warp
    //      redundantly scans the 32 totals and picks its own offset ----
    __shared__ float warp_tot[32];
    if (lane == 0) warp_tot[wid] = warp_total;
    __syncthreads();

    float w  = warp_tot[lane];
    float iw = w;
    #pragma unroll
    for (int d = 1; d < 32; d <<= 1) {
        float tmp = __shfl_down_sync(0xFFFFFFFFu, iw, d);
        if (lane + d < 32) iw += tmp;
    }
    // exclusive suffix (sum of totals of warps after lane) = iw - w
    const float woff = __shfl_sync(0xFFFFFFFFu, iw - w, wid);

    // ---- apply offsets, coalesced store (default policy) ----
    float4* __restrict__ o =
        reinterpret_cast<float4*>(out + base) + wid * F4_PER_WARP + lane;
    #pragma unroll
    for (int i = 0; i < SLOTS; i++) {
        const float off = woff + O[i] + excl[i];
        float4 wv;
        wv.x = r[i].x + off;
        wv.y = r[i].y + off;
        wv.z = r[i].z + off;
        wv.w = r[i].w + off;
        o[i * 32] = wv;
    }
}

extern "C" void kernel_launch(void* const* d_in, const int* in_sizes, int n_in,
                              void* d_out, int out_size) {
    const float* x = (const float*)d_in[0];
    float* out = (float*)d_out;
    const int n = in_sizes[0];          // B * N
    const int rows = n / N_COLS;        // 2048
    revcumsum_kernel<<<rows, THREADS>>>(x, out);
}